// round 9
// baseline (speedup 1.0000x reference)
#include <cuda_runtime.h>
#include <math.h>

#define BDIM   16
#define TDIM   2048
#define FDIM   128
#define LDIM   16
#define LIB    1016
#define NROWS  (BDIM*TDIM)          // 32768

// output offsets (floats)
#define Y_OFF   ((size_t)0)
#define X_OFF   ((size_t)524288)
#define Z_OFF   ((size_t)4718592)
#define J_OFF   ((size_t)5242880)
#define WS_OFF  ((size_t)72351744)
#define WD_OFF  ((size_t)72368000)

// scratch
__device__ float g_amp[BDIM*LDIM*TDIM];          // [B,L,T]
__device__ float g_ang[BDIM*LDIM*TDIM];          // [B,L,T]
__device__ float g_zt [BDIM*LDIM*TDIM];          // [B,L,T]
__device__ __align__(16) float g_Wt[LIB*LDIM];   // W_sindy transposed [d][l]
__device__ unsigned int g_combo[LIB];            // packed (i | j<<8 | k<<16); 49 -> 1.0 sentinel

// fused smem (floats): Wt 16256 | f 32*52=1664 | combo 1016  = 18936 fl = 75744 B
#define SM_F      16256
#define SM_COMBO  (16256 + 1664)
#define FUSED_SMEM_BYTES ((16256 + 1664 + 1016) * 4)

// ---------------------------------------------------------------------------
// K1: encoder. blocks [0,256): z = x @ W_enc^T + b_enc, 2 threads per row.
//     block 256: transpose W_sindy -> g_Wt and build combo table.
// ---------------------------------------------------------------------------
__global__ __launch_bounds__(256) void encoder_kernel(
    const float* __restrict__ x, const float* __restrict__ W_enc,
    const float* __restrict__ b_enc, const float* __restrict__ W_sindy,
    float* __restrict__ z_out)
{
    __shared__ float4 sW[512];
    __shared__ float  sb[16];
    const int tid = threadIdx.x;
    const int bb  = blockIdx.x;

    if (bb == 256) {
        // transpose W_sindy [16][1016] -> g_Wt [1016][16]
        for (int i = tid; i < LDIM * LIB; i += 256) {
            int l = i / LIB;
            int d = i - l * LIB;
            g_Wt[d * 16 + l] = W_sindy[i];
        }
        // combo table (reference feature order: deg1, deg2, deg3, z, amp, ang)
        if (tid < 16) {
            int off = 152;
            for (int a = 0; a < tid; a++) { int n = 16 - a; off += n * (n + 1) / 2; }
            for (int j = tid; j < 16; j++)
                for (int k = j; k < 16; k++)
                    g_combo[off++] = (unsigned)tid | ((unsigned)j << 8) | ((unsigned)k << 16);
        } else if (tid == 16) {
            int d = 0;
            for (int i = 0; i < 16; i++)
                g_combo[d++] = (unsigned)i | (49u << 8) | (49u << 16);
            for (int i = 0; i < 16; i++)
                for (int j = i; j < 16; j++)
                    g_combo[d++] = (unsigned)i | ((unsigned)j << 8) | (49u << 16);
        } else if (tid == 17) {
            int d = 968;
            for (int i = 0; i < 48; i++)
                g_combo[d++] = (unsigned)i | (49u << 8) | (49u << 16);
        }
        return;
    }

    for (int i = tid; i < 512; i += 256) sW[i] = ((const float4*)W_enc)[i];
    if (tid < 16) sb[tid] = b_enc[tid];
    __syncthreads();

    const int gt   = bb * 256 + tid;
    const int row  = gt >> 1;
    const int half = gt & 1;
    const float4* xr = (const float4*)(x + (size_t)row * FDIM) + half * 16;

    float acc[16];
#pragma unroll
    for (int l = 0; l < 16; l++) acc[l] = 0.0f;

#pragma unroll
    for (int c = 0; c < 16; c++) {
        float4 xv = xr[c];
#pragma unroll
        for (int l = 0; l < 16; l++) {
            float4 wv = sW[l * 32 + half * 16 + c];
            acc[l] = fmaf(xv.x, wv.x, acc[l]);
            acc[l] = fmaf(xv.y, wv.y, acc[l]);
            acc[l] = fmaf(xv.z, wv.z, acc[l]);
            acc[l] = fmaf(xv.w, wv.w, acc[l]);
        }
    }
#pragma unroll
    for (int l = 0; l < 16; l++)
        acc[l] += __shfl_xor_sync(0xffffffffu, acc[l], 1);
#pragma unroll
    for (int l = 0; l < 16; l++) acc[l] += sb[l];

    float4* zo = (float4*)(z_out + (size_t)row * LDIM);
    if (half == 0) {
        zo[0] = make_float4(acc[0], acc[1], acc[2],  acc[3]);
        zo[1] = make_float4(acc[4], acc[5], acc[6],  acc[7]);
    } else {
        zo[2] = make_float4(acc[8],  acc[9],  acc[10], acc[11]);
        zo[3] = make_float4(acc[12], acc[13], acc[14], acc[15]);
    }
    const int b = row >> 11;
    const int t = row & 2047;
#pragma unroll
    for (int k = 0; k < 8; k++) {
        int l = half * 8 + k;
        g_zt[((size_t)(b * 16 + l)) * TDIM + t] = acc[l];
    }
}

// ---------------------------------------------------------------------------
// K2: hilbert. 256 blocks: FFT -> H filter -> iFFT per (b,lat), [B,L,T] layout.
// ---------------------------------------------------------------------------
__global__ __launch_bounds__(512) void hilbert_kernel()
{
    __shared__ float2 bufA[2048];
    __shared__ float2 bufB[2048];
    const int tid = threadIdx.x;
    const int seq = blockIdx.x;

    const float* zp = g_zt + (size_t)seq * TDIM;
    for (int t = tid; t < 2048; t += 512)
        bufA[t] = make_float2(zp[t], 0.0f);
    __syncthreads();

    float2* src = bufA;
    float2* dst = bufB;

    for (int p = 0; p < 11; p++) {                 // forward FFT
        const int   len  = 1 << p;
        const float coef = -3.14159265358979323846f / (float)len;
        for (int j = tid; j < 1024; j += 512) {
            const int k = j & (len - 1);
            float2 a  = src[j];
            float2 b2 = src[j + 1024];
            float s, c;
            __sincosf(coef * (float)k, &s, &c);
            float2 wb = make_float2(c * b2.x - s * b2.y, c * b2.y + s * b2.x);
            const int base = 2 * (j - k) + k;
            dst[base]       = make_float2(a.x + wb.x, a.y + wb.y);
            dst[base + len] = make_float2(a.x - wb.x, a.y - wb.y);
        }
        __syncthreads();
        float2* tsw = src; src = dst; dst = tsw;
    }

    for (int t = tid; t < 2048; t += 512) {        // H filter
        float h = (t >= 1 && t < 1024) ? 2.0f : 0.0f;
        src[t].x *= h;
        src[t].y *= h;
    }
    __syncthreads();

    for (int p = 0; p < 11; p++) {                 // inverse FFT
        const int   len  = 1 << p;
        const float coef = 3.14159265358979323846f / (float)len;
        for (int j = tid; j < 1024; j += 512) {
            const int k = j & (len - 1);
            float2 a  = src[j];
            float2 b2 = src[j + 1024];
            float s, c;
            __sincosf(coef * (float)k, &s, &c);
            float2 wb = make_float2(c * b2.x - s * b2.y, c * b2.y + s * b2.x);
            const int base = 2 * (j - k) + k;
            dst[base]       = make_float2(a.x + wb.x, a.y + wb.y);
            dst[base + len] = make_float2(a.x - wb.x, a.y - wb.y);
        }
        __syncthreads();
        float2* tsw = src; src = dst; dst = tsw;
    }

    const float scale = 1.0f / 2048.0f;
    const size_t ob = (size_t)seq * TDIM;
    for (int t = tid; t < 2048; t += 512) {
        float re = src[t].x * scale;
        float im = src[t].y * scale;
        g_amp[ob + t] = sqrtf(re * re + im * im);
        g_ang[ob + t] = atan2f(im, re);
    }
}

// ---------------------------------------------------------------------------
// K3: fused, HOMOGENEOUS blocks. 1024 blocks x 256 threads; block bb owns
// rows [bb*32, bb*32+32) and jac float4 slice [bb*16384, +16384).
// Per block: (1) jac streaming stores (fire-and-forget, drain during compute)
//            (2) smem fill: W_sindy^T + combo + per-row features f
//            (3) Y: 8 threads/row x 127 features (d = s*8+u -> consecutive
//                Wt rows per warp step = conflict-free LDS), shfl-reduce
//            (4) X: x_hat = z @ W_dec^T + b_dec
// Block 1024: copy W_sindy, W_dec to output.
// ---------------------------------------------------------------------------
__global__ __launch_bounds__(256) void fused_kernel(
    const float* __restrict__ W_enc,
    const float* __restrict__ W_dec,   const float* __restrict__ b_dec,
    const float* __restrict__ W_sindy, const float* __restrict__ b_sindy,
    const float* __restrict__ z,       // z region of output blob [B,T,L]
    float* __restrict__ out)
{
    extern __shared__ float smem[];
    const int tid = threadIdx.x;
    const int bb  = blockIdx.x;

    if (bb == 1024) {
        const float4* ws4 = (const float4*)W_sindy;
        float4* o1 = (float4*)(out + WS_OFF);
        for (int i = tid; i < (LDIM * LIB) / 4; i += 256) o1[i] = ws4[i];
        const float4* wd4 = (const float4*)W_dec;
        float4* o2 = (float4*)(out + WD_OFF);
        for (int i = tid; i < (FDIM * LDIM) / 4; i += 256) o2[i] = wd4[i];
        return;
    }

    // ---- (1) jac slice: 16384 float4 per block, 64 per thread ----
    {
        const float4* we4 = (const float4*)W_enc;
        float4* jac4 = (float4*)(out + J_OFF);
        const size_t vbase = (size_t)bb * 16384 + tid;
#pragma unroll 8
        for (int k = 0; k < 64; k++) {
            size_t v = vbase + (size_t)k * 256;
            __stcs(&jac4[v], __ldg(&we4[v & 511]));
        }
    }

    // ---- (2) smem fill ----
    float* s_Wt = smem;
    float* s_f  = smem + SM_F;
    unsigned int* s_combo = (unsigned int*)(smem + SM_COMBO);
    {
        const float4* wt4 = (const float4*)g_Wt;
        float4* d4 = (float4*)s_Wt;
        for (int i = tid; i < (LIB * LDIM) / 4; i += 256) d4[i] = wt4[i];
        for (int i = tid; i < LIB; i += 256) s_combo[i] = g_combo[i];
    }

    const int row_local = tid >> 3;       // 0..31
    const int u         = tid & 7;        // 0..7
    const int row       = bb * 32 + row_local;
    const int b         = row >> 11;
    const int tt        = row & 2047;
    float* f = s_f + row_local * 52;
#pragma unroll
    for (int m = 0; m < 6; m++) {
        int idx = u * 6 + m;              // 0..47
        float val;
        if (idx < 16)      val = z[(size_t)row * LDIM + idx];
        else if (idx < 32) val = g_amp[((size_t)(b * 16 + idx - 16)) * TDIM + tt];
        else               val = g_ang[((size_t)(b * 16 + idx - 32)) * TDIM + tt];
        f[idx] = val;
    }
    if (u == 0) { f[48] = 1.0f; f[49] = 1.0f; f[50] = 1.0f; f[51] = 1.0f; }
    __syncthreads();

    // ---- (3) Y: 127 features per thread, d = s*8+u ----
    float acc[16];
#pragma unroll
    for (int l = 0; l < 16; l++) acc[l] = 0.0f;

#pragma unroll 2
    for (int s = 0; s < 127; s++) {
        const int d = s * 8 + u;
        unsigned int c = s_combo[d];
        float v = f[c & 63u] * f[(c >> 8) & 63u] * f[(c >> 16) & 63u];
        const float4* w4 = (const float4*)(s_Wt + (d << 4));
        float4 w0 = w4[0], w1 = w4[1], w2 = w4[2], w3 = w4[3];
        acc[0]  = fmaf(v, w0.x, acc[0]);  acc[1]  = fmaf(v, w0.y, acc[1]);
        acc[2]  = fmaf(v, w0.z, acc[2]);  acc[3]  = fmaf(v, w0.w, acc[3]);
        acc[4]  = fmaf(v, w1.x, acc[4]);  acc[5]  = fmaf(v, w1.y, acc[5]);
        acc[6]  = fmaf(v, w1.z, acc[6]);  acc[7]  = fmaf(v, w1.w, acc[7]);
        acc[8]  = fmaf(v, w2.x, acc[8]);  acc[9]  = fmaf(v, w2.y, acc[9]);
        acc[10] = fmaf(v, w2.z, acc[10]); acc[11] = fmaf(v, w2.w, acc[11]);
        acc[12] = fmaf(v, w3.x, acc[12]); acc[13] = fmaf(v, w3.y, acc[13]);
        acc[14] = fmaf(v, w3.z, acc[14]); acc[15] = fmaf(v, w3.w, acc[15]);
    }
#pragma unroll
    for (int l = 0; l < 16; l++) {
        acc[l] += __shfl_xor_sync(0xffffffffu, acc[l], 1);
        acc[l] += __shfl_xor_sync(0xffffffffu, acc[l], 2);
        acc[l] += __shfl_xor_sync(0xffffffffu, acc[l], 4);
    }
    if (u == 0) {
        const float4* bs4 = (const float4*)b_sindy;
        float4 b0 = bs4[0], b1 = bs4[1], b2 = bs4[2], b3 = bs4[3];
        float4* yo = (float4*)(out + Y_OFF + (size_t)row * LDIM);
        yo[0] = make_float4(acc[0]  + b0.x, acc[1]  + b0.y, acc[2]  + b0.z, acc[3]  + b0.w);
        yo[1] = make_float4(acc[4]  + b1.x, acc[5]  + b1.y, acc[6]  + b1.z, acc[7]  + b1.w);
        yo[2] = make_float4(acc[8]  + b2.x, acc[9]  + b2.y, acc[10] + b2.z, acc[11] + b2.w);
        yo[3] = make_float4(acc[12] + b3.x, acc[13] + b3.y, acc[14] + b3.z, acc[15] + b3.w);
    }

    // ---- (4) X: 32 rows x 128 cols; thread = (rowgrp, col) ----
    {
        const int col = tid & 127;
        const int rg  = tid >> 7;         // 0..1
        const float4* wd = (const float4*)W_dec;
        float4 w0 = wd[col * 4 + 0];
        float4 w1 = wd[col * 4 + 1];
        float4 w2 = wd[col * 4 + 2];
        float4 w3 = wd[col * 4 + 3];
        float  bd = b_dec[col];
        const int rbase = bb * 32 + rg * 16;
#pragma unroll 4
        for (int rr = 0; rr < 16; rr++) {
            const float4* zr = (const float4*)(z + (size_t)(rbase + rr) * LDIM);
            float4 z0 = __ldg(zr + 0), z1 = __ldg(zr + 1);
            float4 z2 = __ldg(zr + 2), z3 = __ldg(zr + 3);
            float v = bd;
            v = fmaf(z0.x, w0.x, v); v = fmaf(z0.y, w0.y, v);
            v = fmaf(z0.z, w0.z, v); v = fmaf(z0.w, w0.w, v);
            v = fmaf(z1.x, w1.x, v); v = fmaf(z1.y, w1.y, v);
            v = fmaf(z1.z, w1.z, v); v = fmaf(z1.w, w1.w, v);
            v = fmaf(z2.x, w2.x, v); v = fmaf(z2.y, w2.y, v);
            v = fmaf(z2.z, w2.z, v); v = fmaf(z2.w, w2.w, v);
            v = fmaf(z3.x, w3.x, v); v = fmaf(z3.y, w3.y, v);
            v = fmaf(z3.z, w3.z, v); v = fmaf(z3.w, w3.w, v);
            out[X_OFF + (size_t)(rbase + rr) * FDIM + col] = v;
        }
    }
}

// ---------------------------------------------------------------------------
extern "C" void kernel_launch(void* const* d_in, const int* in_sizes, int n_in,
                              void* d_out, int out_size)
{
    const float* x       = (const float*)d_in[0];
    const float* W_enc   = (const float*)d_in[1];
    const float* b_enc   = (const float*)d_in[2];
    const float* W_dec   = (const float*)d_in[3];
    const float* b_dec   = (const float*)d_in[4];
    const float* W_sindy = (const float*)d_in[5];
    const float* b_sindy = (const float*)d_in[6];
    float* out = (float*)d_out;

    float* z_out = out + Z_OFF;

    encoder_kernel<<<257, 256>>>(x, W_enc, b_enc, W_sindy, z_out);
    hilbert_kernel<<<256, 512>>>();

    static int smem_set = 0;
    if (!smem_set) {
        cudaFuncSetAttribute(fused_kernel,
                             cudaFuncAttributeMaxDynamicSharedMemorySize,
                             FUSED_SMEM_BYTES);
        smem_set = 1;
    }
    fused_kernel<<<1025, 256, FUSED_SMEM_BYTES>>>(
        W_enc, W_dec, b_dec, W_sindy, b_sindy, z_out, out);
}

// round 10
// speedup vs baseline: 1.8035x; 1.8035x over previous
#include <cuda_runtime.h>
#include <math.h>

#define BDIM   16
#define TDIM   2048
#define FDIM   128
#define LDIM   16
#define LIB    1016
#define NROWS  (BDIM*TDIM)          // 32768

// output offsets (floats)
#define Y_OFF   ((size_t)0)
#define X_OFF   ((size_t)524288)
#define Z_OFF   ((size_t)4718592)
#define J_OFF   ((size_t)5242880)
#define WS_OFF  ((size_t)72351744)
#define WD_OFF  ((size_t)72368000)

// scratch
__device__ float g_amp[BDIM*LDIM*TDIM];          // [B,L,T]
__device__ float g_ang[BDIM*LDIM*TDIM];          // [B,L,T]
__device__ float g_zt [BDIM*LDIM*TDIM];          // [B,L,T]
__device__ __align__(16) float g_Wt[LIB*LDIM];   // W_sindy transposed [d][l]
__device__ unsigned int g_combo[LIB];            // packed (i | j<<8 | k<<16); 49 -> 1.0

// fused smem (floats): Wt 16256 | f 32*53=1696 | combo 1016 | red 4096  = 23064 fl
#define SM_F      16256
#define SM_COMBO  (16256 + 1696)
#define SM_RED    (16256 + 1696 + 1016)
#define FUSED_SMEM_BYTES ((16256 + 1696 + 1016 + 4096) * 4)

// ---------------------------------------------------------------------------
// K1: encoder. blocks [0,512): z = x @ W_enc^T + b_enc, 4 threads per row.
//     block 512: transpose W_sindy -> g_Wt and build combo table.
// ---------------------------------------------------------------------------
__global__ __launch_bounds__(256) void encoder_kernel(
    const float* __restrict__ x, const float* __restrict__ W_enc,
    const float* __restrict__ b_enc, const float* __restrict__ W_sindy,
    float* __restrict__ z_out)
{
    __shared__ float4 sW[512];
    __shared__ float  sb[16];
    const int tid = threadIdx.x;
    const int bb  = blockIdx.x;

    if (bb == 512) {
        // transpose W_sindy [16][1016] -> g_Wt [1016][16]
        for (int i = tid; i < LDIM * LIB; i += 256) {
            int l = i / LIB;
            int d = i - l * LIB;
            g_Wt[d * 16 + l] = W_sindy[i];
        }
        // combo table (reference feature order: deg1, deg2, deg3, z, amp, ang)
        if (tid < 16) {
            int off = 152;
            for (int a = 0; a < tid; a++) { int n = 16 - a; off += n * (n + 1) / 2; }
            for (int j = tid; j < 16; j++)
                for (int k = j; k < 16; k++)
                    g_combo[off++] = (unsigned)tid | ((unsigned)j << 8) | ((unsigned)k << 16);
        } else if (tid == 16) {
            int d = 0;
            for (int i = 0; i < 16; i++)
                g_combo[d++] = (unsigned)i | (49u << 8) | (49u << 16);
            for (int i = 0; i < 16; i++)
                for (int j = i; j < 16; j++)
                    g_combo[d++] = (unsigned)i | ((unsigned)j << 8) | (49u << 16);
        } else if (tid == 17) {
            int d = 968;
            for (int i = 0; i < 48; i++)
                g_combo[d++] = (unsigned)i | (49u << 8) | (49u << 16);
        }
        return;
    }

    for (int i = tid; i < 512; i += 256) sW[i] = ((const float4*)W_enc)[i];
    if (tid < 16) sb[tid] = b_enc[tid];
    __syncthreads();

    const int gt  = bb * 256 + tid;
    const int row = gt >> 2;
    const int q   = gt & 3;
    const float4* xr = (const float4*)(x + (size_t)row * FDIM) + q * 8;

    float acc[16];
#pragma unroll
    for (int l = 0; l < 16; l++) acc[l] = 0.0f;

#pragma unroll
    for (int c = 0; c < 8; c++) {
        float4 xv = xr[c];
#pragma unroll
        for (int l = 0; l < 16; l++) {
            float4 wv = sW[l * 32 + q * 8 + c];
            acc[l] = fmaf(xv.x, wv.x, acc[l]);
            acc[l] = fmaf(xv.y, wv.y, acc[l]);
            acc[l] = fmaf(xv.z, wv.z, acc[l]);
            acc[l] = fmaf(xv.w, wv.w, acc[l]);
        }
    }
#pragma unroll
    for (int l = 0; l < 16; l++) {
        acc[l] += __shfl_xor_sync(0xffffffffu, acc[l], 1);
        acc[l] += __shfl_xor_sync(0xffffffffu, acc[l], 2);
    }
#pragma unroll
    for (int l = 0; l < 16; l++) acc[l] += sb[l];

    // each quarter writes its own float4 of z and its 4 transposed lanes
    float4* zo = (float4*)(z_out + (size_t)row * LDIM);
    zo[q] = make_float4(acc[q*4+0], acc[q*4+1], acc[q*4+2], acc[q*4+3]);

    const int b = row >> 11;
    const int t = row & 2047;
#pragma unroll
    for (int k = 0; k < 4; k++) {
        int l = q * 4 + k;
        g_zt[((size_t)(b * 16 + l)) * TDIM + t] = acc[l];
    }
}

// ---------------------------------------------------------------------------
// K2: hilbert. 256 blocks: FFT -> H filter -> iFFT per (b,lat), [B,L,T] layout.
// ---------------------------------------------------------------------------
__global__ __launch_bounds__(512) void hilbert_kernel()
{
    __shared__ float2 bufA[2048];
    __shared__ float2 bufB[2048];
    const int tid = threadIdx.x;
    const int seq = blockIdx.x;

    const float* zp = g_zt + (size_t)seq * TDIM;
    for (int t = tid; t < 2048; t += 512)
        bufA[t] = make_float2(zp[t], 0.0f);
    __syncthreads();

    float2* src = bufA;
    float2* dst = bufB;

    for (int p = 0; p < 11; p++) {                 // forward FFT
        const int   len  = 1 << p;
        const float coef = -3.14159265358979323846f / (float)len;
        for (int j = tid; j < 1024; j += 512) {
            const int k = j & (len - 1);
            float2 a  = src[j];
            float2 b2 = src[j + 1024];
            float s, c;
            __sincosf(coef * (float)k, &s, &c);
            float2 wb = make_float2(c * b2.x - s * b2.y, c * b2.y + s * b2.x);
            const int base = 2 * (j - k) + k;
            dst[base]       = make_float2(a.x + wb.x, a.y + wb.y);
            dst[base + len] = make_float2(a.x - wb.x, a.y - wb.y);
        }
        __syncthreads();
        float2* tsw = src; src = dst; dst = tsw;
    }

    for (int t = tid; t < 2048; t += 512) {        // H filter
        float h = (t >= 1 && t < 1024) ? 2.0f : 0.0f;
        src[t].x *= h;
        src[t].y *= h;
    }
    __syncthreads();

    for (int p = 0; p < 11; p++) {                 // inverse FFT
        const int   len  = 1 << p;
        const float coef = 3.14159265358979323846f / (float)len;
        for (int j = tid; j < 1024; j += 512) {
            const int k = j & (len - 1);
            float2 a  = src[j];
            float2 b2 = src[j + 1024];
            float s, c;
            __sincosf(coef * (float)k, &s, &c);
            float2 wb = make_float2(c * b2.x - s * b2.y, c * b2.y + s * b2.x);
            const int base = 2 * (j - k) + k;
            dst[base]       = make_float2(a.x + wb.x, a.y + wb.y);
            dst[base + len] = make_float2(a.x - wb.x, a.y - wb.y);
        }
        __syncthreads();
        float2* tsw = src; src = dst; dst = tsw;
    }

    const float scale = 1.0f / 2048.0f;
    const size_t ob = (size_t)seq * TDIM;
    for (int t = tid; t < 2048; t += 512) {
        float re = src[t].x * scale;
        float im = src[t].y * scale;
        g_amp[ob + t] = sqrtf(re * re + im * im);
        g_ang[ob + t] = atan2f(im, re);
    }
}

// ---------------------------------------------------------------------------
// K3: fused, homogeneous. 1024 blocks x 256 threads; block bb owns rows
// [bb*32, +32) and jac float4 slice [bb*16384, +16384).
// Y mapping: WARP = feature octant (127 consecutive d), LANE = row.
//   -> weight LDS are same-address broadcasts (conflict-free, ~free),
//      f gathers lane-indexed with stride 53 (odd -> conflict-free).
// Cross-warp reduce over the 8 octants through smem, then bias + store.
// Block 1024: copy W_sindy, W_dec.
// ---------------------------------------------------------------------------
__global__ __launch_bounds__(256) void fused_kernel(
    const float* __restrict__ W_enc,
    const float* __restrict__ W_dec,   const float* __restrict__ b_dec,
    const float* __restrict__ W_sindy, const float* __restrict__ b_sindy,
    const float* __restrict__ z,       // z region of output blob [B,T,L]
    float* __restrict__ out)
{
    extern __shared__ float smem[];
    const int tid = threadIdx.x;
    const int bb  = blockIdx.x;

    if (bb == 1024) {
        const float4* ws4 = (const float4*)W_sindy;
        float4* o1 = (float4*)(out + WS_OFF);
        for (int i = tid; i < (LDIM * LIB) / 4; i += 256) o1[i] = ws4[i];
        const float4* wd4 = (const float4*)W_dec;
        float4* o2 = (float4*)(out + WD_OFF);
        for (int i = tid; i < (FDIM * LDIM) / 4; i += 256) o2[i] = wd4[i];
        return;
    }

    // ---- (1) jac slice: 16384 float4, fire-and-forget streaming stores ----
    {
        const float4* we4 = (const float4*)W_enc;
        float4* jac4 = (float4*)(out + J_OFF);
        const size_t vbase = (size_t)bb * 16384 + tid;
#pragma unroll 8
        for (int k = 0; k < 64; k++) {
            size_t v = vbase + (size_t)k * 256;
            __stcs(&jac4[v], __ldg(&we4[v & 511]));
        }
    }

    // ---- (2) smem fill ----
    float* s_Wt = smem;                       // [1016][16]
    float* s_f  = smem + SM_F;                // [32][53]
    unsigned int* s_combo = (unsigned int*)(smem + SM_COMBO);
    float* s_red = smem + SM_RED;             // [8][32][16]
    {
        const float4* wt4 = (const float4*)g_Wt;
        float4* d4 = (float4*)s_Wt;
        for (int i = tid; i < (LIB * LDIM) / 4; i += 256) d4[i] = wt4[i];
        for (int i = tid; i < LIB; i += 256) s_combo[i] = g_combo[i];
    }

    const int u    = tid >> 5;        // warp id = feature octant
    const int lane = tid & 31;        // row within tile
    const int row  = bb * 32 + lane;
    const int b    = row >> 11;
    const int tt   = row & 2047;
    float* f = s_f + lane * 53;
    // warp u fills feature slots u*6 .. u*6+5 for its lane's row
#pragma unroll
    for (int m = 0; m < 6; m++) {
        int idx = u * 6 + m;              // 0..47
        float val;
        if (idx < 16)      val = z[(size_t)row * LDIM + idx];
        else if (idx < 32) val = g_amp[((size_t)(b * 16 + idx - 16)) * TDIM + tt];
        else               val = g_ang[((size_t)(b * 16 + idx - 32)) * TDIM + tt];
        f[idx] = val;
    }
    if (u == 0) { f[48] = 1.0f; f[49] = 1.0f; f[50] = 1.0f; f[51] = 1.0f; f[52] = 1.0f; }
    __syncthreads();

    // ---- (3) Y: warp u walks d = u*127 .. u*127+126 (consecutive) ----
    float acc[16];
#pragma unroll
    for (int l = 0; l < 16; l++) acc[l] = 0.0f;

    int d = u * 127;
#pragma unroll 2
    for (int s = 0; s < 127; s++, d++) {
        unsigned int c = s_combo[d];                       // broadcast
        float v = f[c & 63u] * f[(c >> 8) & 63u] * f[(c >> 16) & 63u];
        const float4* w4 = (const float4*)(s_Wt + (d << 4)); // broadcast
        float4 w0 = w4[0], w1 = w4[1], w2 = w4[2], w3 = w4[3];
        acc[0]  = fmaf(v, w0.x, acc[0]);  acc[1]  = fmaf(v, w0.y, acc[1]);
        acc[2]  = fmaf(v, w0.z, acc[2]);  acc[3]  = fmaf(v, w0.w, acc[3]);
        acc[4]  = fmaf(v, w1.x, acc[4]);  acc[5]  = fmaf(v, w1.y, acc[5]);
        acc[6]  = fmaf(v, w1.z, acc[6]);  acc[7]  = fmaf(v, w1.w, acc[7]);
        acc[8]  = fmaf(v, w2.x, acc[8]);  acc[9]  = fmaf(v, w2.y, acc[9]);
        acc[10] = fmaf(v, w2.z, acc[10]); acc[11] = fmaf(v, w2.w, acc[11]);
        acc[12] = fmaf(v, w3.x, acc[12]); acc[13] = fmaf(v, w3.y, acc[13]);
        acc[14] = fmaf(v, w3.z, acc[14]); acc[15] = fmaf(v, w3.w, acc[15]);
    }
    // stash partial sums: s_red[u][lane][l]
    {
        float4* r4 = (float4*)(s_red + (u * 32 + lane) * 16);
        r4[0] = make_float4(acc[0],  acc[1],  acc[2],  acc[3]);
        r4[1] = make_float4(acc[4],  acc[5],  acc[6],  acc[7]);
        r4[2] = make_float4(acc[8],  acc[9],  acc[10], acc[11]);
        r4[3] = make_float4(acc[12], acc[13], acc[14], acc[15]);
    }
    __syncthreads();

    // ---- (4) reduce over 8 octants + bias + store y_hat ----
#pragma unroll
    for (int it = 0; it < 2; it++) {
        int pp = it * 256 + tid;          // 0..511 -> (rowlocal, l)
        float sum = 0.0f;
#pragma unroll
        for (int w = 0; w < 8; w++) sum += s_red[w * 512 + pp];
        sum += __ldg(&b_sindy[pp & 15]);
        out[Y_OFF + ((size_t)bb * 32) * LDIM + pp] = sum;
    }

    // ---- (5) X: x_hat = z @ W_dec^T + b_dec ----
    {
        const int col = tid & 127;
        const int rg  = tid >> 7;         // 0..1
        const float4* wd = (const float4*)W_dec;
        float4 w0 = wd[col * 4 + 0];
        float4 w1 = wd[col * 4 + 1];
        float4 w2 = wd[col * 4 + 2];
        float4 w3 = wd[col * 4 + 3];
        float  bd = b_dec[col];
        const int rbase = bb * 32 + rg * 16;
#pragma unroll 4
        for (int rr = 0; rr < 16; rr++) {
            const float4* zr = (const float4*)(z + (size_t)(rbase + rr) * LDIM);
            float4 z0 = __ldg(zr + 0), z1 = __ldg(zr + 1);
            float4 z2 = __ldg(zr + 2), z3 = __ldg(zr + 3);
            float v = bd;
            v = fmaf(z0.x, w0.x, v); v = fmaf(z0.y, w0.y, v);
            v = fmaf(z0.z, w0.z, v); v = fmaf(z0.w, w0.w, v);
            v = fmaf(z1.x, w1.x, v); v = fmaf(z1.y, w1.y, v);
            v = fmaf(z1.z, w1.z, v); v = fmaf(z1.w, w1.w, v);
            v = fmaf(z2.x, w2.x, v); v = fmaf(z2.y, w2.y, v);
            v = fmaf(z2.z, w2.z, v); v = fmaf(z2.w, w2.w, v);
            v = fmaf(z3.x, w3.x, v); v = fmaf(z3.y, w3.y, v);
            v = fmaf(z3.z, w3.z, v); v = fmaf(z3.w, w3.w, v);
            out[X_OFF + (size_t)(rbase + rr) * FDIM + col] = v;
        }
    }
}

// ---------------------------------------------------------------------------
extern "C" void kernel_launch(void* const* d_in, const int* in_sizes, int n_in,
                              void* d_out, int out_size)
{
    const float* x       = (const float*)d_in[0];
    const float* W_enc   = (const float*)d_in[1];
    const float* b_enc   = (const float*)d_in[2];
    const float* W_dec   = (const float*)d_in[3];
    const float* b_dec   = (const float*)d_in[4];
    const float* W_sindy = (const float*)d_in[5];
    const float* b_sindy = (const float*)d_in[6];
    float* out = (float*)d_out;

    float* z_out = out + Z_OFF;

    encoder_kernel<<<513, 256>>>(x, W_enc, b_enc, W_sindy, z_out);
    hilbert_kernel<<<256, 512>>>();

    static int smem_set = 0;
    if (!smem_set) {
        cudaFuncSetAttribute(fused_kernel,
                             cudaFuncAttributeMaxDynamicSharedMemorySize,
                             FUSED_SMEM_BYTES);
        smem_set = 1;
    }
    fused_kernel<<<1025, 256, FUSED_SMEM_BYTES>>>(
        W_enc, W_dec, b_dec, W_sindy, b_sindy, z_out, out);
}

// round 11
// speedup vs baseline: 2.2018x; 1.2209x over previous
#include <cuda_runtime.h>
#include <math.h>

#define BDIM   16
#define TDIM   2048
#define FDIM   128
#define LDIM   16
#define LIB    1016
#define NROWS  (BDIM*TDIM)          // 32768

// output offsets (floats)
#define Y_OFF   ((size_t)0)
#define X_OFF   ((size_t)524288)
#define Z_OFF   ((size_t)4718592)
#define J_OFF   ((size_t)5242880)
#define WS_OFF  ((size_t)72351744)
#define WD_OFF  ((size_t)72368000)

// jac float4 regions: encoder 96MB | hilbert 80MB | fused 92.3MB
#define JAC_E_BEG ((size_t)0)
#define JAC_E_LEN ((size_t)6291456)
#define JAC_H_BEG ((size_t)6291456)
#define JAC_H_LEN ((size_t)5242880)
#define JAC_F_BEG ((size_t)11534336)
#define JAC_F_LEN ((size_t)5242880)   // 1024 blocks * 5120

// scratch
__device__ float g_amp[BDIM*LDIM*TDIM];          // [B,L,T]
__device__ float g_ang[BDIM*LDIM*TDIM];          // [B,L,T]
__device__ float g_zt [BDIM*LDIM*TDIM];          // [B,L,T]
__device__ __align__(16) float g_Wt[LIB*LDIM];   // W_sindy transposed [d][l]
__device__ unsigned int g_combo[LIB];            // packed (i | j<<8 | k<<16); 49 -> 1.0

// fused smem (floats): Wt 16256 | f 32*53=1696 | combo 1016 | red 4096
#define SM_F      16256
#define SM_COMBO  (16256 + 1696)
#define SM_RED    (16256 + 1696 + 1016)
#define FUSED_SMEM_BYTES ((16256 + 1696 + 1016 + 4096) * 4)

// ---------------------------------------------------------------------------
__device__ __forceinline__ void jac_store(float* __restrict__ out,
                                          const float4* __restrict__ tile,
                                          size_t region_beg, size_t region_len,
                                          int jb, int nblk, int tid, int nthr)
{
    float4* jac4 = (float4*)(out + J_OFF);
    const size_t stride = (size_t)nblk * nthr;
    for (size_t v = (size_t)jb * nthr + tid; v < region_len; v += stride) {
        size_t gidx = region_beg + v;
        __stcs(&jac4[gidx], tile[gidx & 511]);
    }
}

// ---------------------------------------------------------------------------
// K1: encoder. blocks [0,128): z = x @ W_enc^T + b_enc, ONE thread per row
//     (R1 mapping: latency-hiding via 32 independent float4 loads/thread).
//     block 128: transpose W_sindy -> g_Wt + combo table.
//     blocks [129,385): jac region E (96 MB, drains behind compute).
// ---------------------------------------------------------------------------
__global__ __launch_bounds__(256) void encoder_kernel(
    const float* __restrict__ x, const float* __restrict__ W_enc,
    const float* __restrict__ b_enc, const float* __restrict__ W_sindy,
    float* __restrict__ z_out, float* __restrict__ out)
{
    __shared__ float4 sW[512];
    __shared__ float  sb[16];
    const int tid = threadIdx.x;
    const int bb  = blockIdx.x;

    if (bb == 128) {
        for (int i = tid; i < LDIM * LIB; i += 256) {
            int l = i / LIB;
            int d = i - l * LIB;
            g_Wt[d * 16 + l] = W_sindy[i];
        }
        if (tid < 16) {
            int off = 152;
            for (int a = 0; a < tid; a++) { int n = 16 - a; off += n * (n + 1) / 2; }
            for (int j = tid; j < 16; j++)
                for (int k = j; k < 16; k++)
                    g_combo[off++] = (unsigned)tid | ((unsigned)j << 8) | ((unsigned)k << 16);
        } else if (tid == 16) {
            int d = 0;
            for (int i = 0; i < 16; i++)
                g_combo[d++] = (unsigned)i | (49u << 8) | (49u << 16);
            for (int i = 0; i < 16; i++)
                for (int j = i; j < 16; j++)
                    g_combo[d++] = (unsigned)i | ((unsigned)j << 8) | (49u << 16);
        } else if (tid == 17) {
            int d = 968;
            for (int i = 0; i < 48; i++)
                g_combo[d++] = (unsigned)i | (49u << 8) | (49u << 16);
        }
        return;
    }

    for (int i = tid; i < 512; i += 256) sW[i] = ((const float4*)W_enc)[i];

    if (bb >= 129) {
        __syncthreads();
        jac_store(out, sW, JAC_E_BEG, JAC_E_LEN, bb - 129, 256, tid, 256);
        return;
    }

    if (tid < 16) sb[tid] = b_enc[tid];
    __syncthreads();

    const int row = bb * 256 + tid;
    const float4* xr = (const float4*)(x + (size_t)row * FDIM);

    float acc[16];
#pragma unroll
    for (int l = 0; l < 16; l++) acc[l] = sb[l];

#pragma unroll 4
    for (int c = 0; c < 32; c++) {
        float4 xv = xr[c];
#pragma unroll
        for (int l = 0; l < 16; l++) {
            float4 wv = sW[l * 32 + c];
            acc[l] = fmaf(xv.x, wv.x, acc[l]);
            acc[l] = fmaf(xv.y, wv.y, acc[l]);
            acc[l] = fmaf(xv.z, wv.z, acc[l]);
            acc[l] = fmaf(xv.w, wv.w, acc[l]);
        }
    }
    float4* zo = (float4*)(z_out + (size_t)row * LDIM);
    zo[0] = make_float4(acc[0],  acc[1],  acc[2],  acc[3]);
    zo[1] = make_float4(acc[4],  acc[5],  acc[6],  acc[7]);
    zo[2] = make_float4(acc[8],  acc[9],  acc[10], acc[11]);
    zo[3] = make_float4(acc[12], acc[13], acc[14], acc[15]);

    const int b = row >> 11;
    const int t = row & 2047;
#pragma unroll
    for (int k = 0; k < 16; k++)
        g_zt[((size_t)(b * 16 + k)) * TDIM + t] = acc[k];
}

// ---------------------------------------------------------------------------
// K2: hilbert. blocks [0,256): 1024 threads, 1 butterfly/thread/stage.
//     blocks [256,384): jac region H (80 MB).
// ---------------------------------------------------------------------------
__global__ __launch_bounds__(1024) void hilbert_kernel(
    const float* __restrict__ W_enc, float* __restrict__ out)
{
    __shared__ float2 bufA[2048];
    __shared__ float2 bufB[2048];
    const int tid = threadIdx.x;
    const int bb  = blockIdx.x;

    if (bb >= 256) {
        float4* tile = (float4*)bufA;
        const float4* we4 = (const float4*)W_enc;
        if (tid < 512) tile[tid] = we4[tid];
        __syncthreads();
        jac_store(out, tile, JAC_H_BEG, JAC_H_LEN, bb - 256, 128, tid, 1024);
        return;
    }

    const int seq = bb;
    const float* zp = g_zt + (size_t)seq * TDIM;
    bufA[tid]        = make_float2(zp[tid], 0.0f);
    bufA[tid + 1024] = make_float2(zp[tid + 1024], 0.0f);
    __syncthreads();

    float2* src = bufA;
    float2* dst = bufB;

#pragma unroll 1
    for (int p = 0; p < 11; p++) {                 // forward FFT
        const int   len  = 1 << p;
        const float coef = -3.14159265358979323846f / (float)len;
        const int j = tid;
        const int k = j & (len - 1);
        float2 a  = src[j];
        float2 b2 = src[j + 1024];
        float s, c;
        __sincosf(coef * (float)k, &s, &c);
        float2 wb = make_float2(c * b2.x - s * b2.y, c * b2.y + s * b2.x);
        const int base = 2 * (j - k) + k;
        dst[base]       = make_float2(a.x + wb.x, a.y + wb.y);
        dst[base + len] = make_float2(a.x - wb.x, a.y - wb.y);
        __syncthreads();
        float2* tsw = src; src = dst; dst = tsw;
    }

    {   // H filter: H[0]=0, H[1..1023]=2, H[1024..2047]=0
        float h0 = (tid >= 1) ? 2.0f : 0.0f;
        src[tid].x *= h0;  src[tid].y *= h0;
        src[tid + 1024].x = 0.0f; src[tid + 1024].y = 0.0f;
    }
    __syncthreads();

#pragma unroll 1
    for (int p = 0; p < 11; p++) {                 // inverse FFT
        const int   len  = 1 << p;
        const float coef = 3.14159265358979323846f / (float)len;
        const int j = tid;
        const int k = j & (len - 1);
        float2 a  = src[j];
        float2 b2 = src[j + 1024];
        float s, c;
        __sincosf(coef * (float)k, &s, &c);
        float2 wb = make_float2(c * b2.x - s * b2.y, c * b2.y + s * b2.x);
        const int base = 2 * (j - k) + k;
        dst[base]       = make_float2(a.x + wb.x, a.y + wb.y);
        dst[base + len] = make_float2(a.x - wb.x, a.y - wb.y);
        __syncthreads();
        float2* tsw = src; src = dst; dst = tsw;
    }

    const float scale = 1.0f / 2048.0f;
    const size_t ob = (size_t)seq * TDIM;
#pragma unroll
    for (int it = 0; it < 2; it++) {
        int t = tid + it * 1024;
        float re = src[t].x * scale;
        float im = src[t].y * scale;
        g_amp[ob + t] = sqrtf(re * re + im * im);
        g_ang[ob + t] = atan2f(im, re);
    }
}

// ---------------------------------------------------------------------------
// K3: fused, homogeneous (R10 structure). 1024 blocks x 256 threads; block bb
// owns rows [bb*32,+32) and jac slice F_BEG + [bb*5120, +5120).
// Y: warp = feature octant (broadcast weights via f32x2 packed FMA),
//    lane = row (f stride 53, conflict-free). Cross-warp reduce via smem.
// Block 1024: copy W_sindy, W_dec.
// ---------------------------------------------------------------------------
__global__ __launch_bounds__(256) void fused_kernel(
    const float* __restrict__ W_enc,
    const float* __restrict__ W_dec,   const float* __restrict__ b_dec,
    const float* __restrict__ W_sindy, const float* __restrict__ b_sindy,
    const float* __restrict__ z,       // z region of output blob [B,T,L]
    float* __restrict__ out)
{
    extern __shared__ float smem[];
    const int tid = threadIdx.x;
    const int bb  = blockIdx.x;

    if (bb == 1024) {
        const float4* ws4 = (const float4*)W_sindy;
        float4* o1 = (float4*)(out + WS_OFF);
        for (int i = tid; i < (LDIM * LIB) / 4; i += 256) o1[i] = ws4[i];
        const float4* wd4 = (const float4*)W_dec;
        float4* o2 = (float4*)(out + WD_OFF);
        for (int i = tid; i < (FDIM * LDIM) / 4; i += 256) o2[i] = wd4[i];
        return;
    }

    // ---- (1) jac slice: 5120 float4 per block (20/thread) ----
    {
        const float4* we4 = (const float4*)W_enc;
        float4* jac4 = (float4*)(out + J_OFF);
        const size_t vbase = JAC_F_BEG + (size_t)bb * 5120 + tid;
#pragma unroll 5
        for (int k = 0; k < 20; k++) {
            size_t v = vbase + (size_t)k * 256;
            __stcs(&jac4[v], __ldg(&we4[v & 511]));
        }
    }

    // ---- (2) smem fill ----
    float* s_Wt = smem;                       // [1016][16]
    float* s_f  = smem + SM_F;                // [32][53]
    unsigned int* s_combo = (unsigned int*)(smem + SM_COMBO);
    float* s_red = smem + SM_RED;             // [8][32][16]
    {
        const float4* wt4 = (const float4*)g_Wt;
        float4* d4 = (float4*)s_Wt;
        for (int i = tid; i < (LIB * LDIM) / 4; i += 256) d4[i] = wt4[i];
        for (int i = tid; i < LIB; i += 256) s_combo[i] = g_combo[i];
    }

    const int u    = tid >> 5;        // warp id = feature octant
    const int lane = tid & 31;        // row within tile
    const int row  = bb * 32 + lane;
    const int b    = row >> 11;
    const int tt   = row & 2047;
    float* f = s_f + lane * 53;
#pragma unroll
    for (int m = 0; m < 6; m++) {
        int idx = u * 6 + m;              // 0..47
        float val;
        if (idx < 16)      val = z[(size_t)row * LDIM + idx];
        else if (idx < 32) val = g_amp[((size_t)(b * 16 + idx - 16)) * TDIM + tt];
        else               val = g_ang[((size_t)(b * 16 + idx - 32)) * TDIM + tt];
        f[idx] = val;
    }
    if (u == 0) { f[48] = 1.0f; f[49] = 1.0f; f[50] = 1.0f; f[51] = 1.0f; f[52] = 1.0f; }
    __syncthreads();

    // ---- (3) Y: warp u walks d = u*127..u*127+126, packed f32x2 FMA ----
    unsigned long long A0 = 0, A1 = 0, A2 = 0, A3 = 0,
                       A4 = 0, A5 = 0, A6 = 0, A7 = 0;
    int d = u * 127;
#pragma unroll 2
    for (int s = 0; s < 127; s++, d++) {
        unsigned int c = s_combo[d];                       // broadcast
        float v = f[c & 63u] * f[(c >> 8) & 63u] * f[(c >> 16) & 63u];
        unsigned long long pk;
        asm("mov.b64 %0,{%1,%1};" : "=l"(pk) : "r"(__float_as_uint(v)));
        const ulonglong2* w2 = (const ulonglong2*)(s_Wt + (d << 4)); // broadcast
        ulonglong2 p0 = w2[0], p1 = w2[1];
        asm("fma.rn.f32x2 %0,%1,%2,%0;" : "+l"(A0) : "l"(pk), "l"(p0.x));
        asm("fma.rn.f32x2 %0,%1,%2,%0;" : "+l"(A1) : "l"(pk), "l"(p0.y));
        asm("fma.rn.f32x2 %0,%1,%2,%0;" : "+l"(A2) : "l"(pk), "l"(p1.x));
        asm("fma.rn.f32x2 %0,%1,%2,%0;" : "+l"(A3) : "l"(pk), "l"(p1.y));
        const ulonglong2* w3 = w2 + 2;
        ulonglong2 p2 = w3[0], p3 = w3[1];
        asm("fma.rn.f32x2 %0,%1,%2,%0;" : "+l"(A4) : "l"(pk), "l"(p2.x));
        asm("fma.rn.f32x2 %0,%1,%2,%0;" : "+l"(A5) : "l"(pk), "l"(p2.y));
        asm("fma.rn.f32x2 %0,%1,%2,%0;" : "+l"(A6) : "l"(pk), "l"(p3.x));
        asm("fma.rn.f32x2 %0,%1,%2,%0;" : "+l"(A7) : "l"(pk), "l"(p3.y));
    }
    // stash partials: s_red[u][lane][l]
    {
        ulonglong2* r2 = (ulonglong2*)(s_red + (u * 32 + lane) * 16);
        ulonglong2 q;
        q.x = A0; q.y = A1; r2[0] = q;
        q.x = A2; q.y = A3; r2[1] = q;
        q.x = A4; q.y = A5; r2[2] = q;
        q.x = A6; q.y = A7; r2[3] = q;
    }
    __syncthreads();

    // ---- (4) reduce over 8 octants + bias + store y_hat ----
#pragma unroll
    for (int it = 0; it < 2; it++) {
        int pp = it * 256 + tid;          // 0..511 -> (rowlocal, l)
        float sum = 0.0f;
#pragma unroll
        for (int w = 0; w < 8; w++) sum += s_red[w * 512 + pp];
        sum += __ldg(&b_sindy[pp & 15]);
        out[Y_OFF + ((size_t)bb * 32) * LDIM + pp] = sum;
    }

    // ---- (5) X: x_hat = z @ W_dec^T + b_dec ----
    {
        const int col = tid & 127;
        const int rg  = tid >> 7;         // 0..1
        const float4* wd = (const float4*)W_dec;
        float4 w0 = wd[col * 4 + 0];
        float4 w1 = wd[col * 4 + 1];
        float4 w2 = wd[col * 4 + 2];
        float4 w3 = wd[col * 4 + 3];
        float  bd = b_dec[col];
        const int rbase = bb * 32 + rg * 16;
#pragma unroll 4
        for (int rr = 0; rr < 16; rr++) {
            const float4* zr = (const float4*)(z + (size_t)(rbase + rr) * LDIM);
            float4 z0 = __ldg(zr + 0), z1 = __ldg(zr + 1);
            float4 z2 = __ldg(zr + 2), z3 = __ldg(zr + 3);
            float v = bd;
            v = fmaf(z0.x, w0.x, v); v = fmaf(z0.y, w0.y, v);
            v = fmaf(z0.z, w0.z, v); v = fmaf(z0.w, w0.w, v);
            v = fmaf(z1.x, w1.x, v); v = fmaf(z1.y, w1.y, v);
            v = fmaf(z1.z, w1.z, v); v = fmaf(z1.w, w1.w, v);
            v = fmaf(z2.x, w2.x, v); v = fmaf(z2.y, w2.y, v);
            v = fmaf(z2.z, w2.z, v); v = fmaf(z2.w, w2.w, v);
            v = fmaf(z3.x, w3.x, v); v = fmaf(z3.y, w3.y, v);
            v = fmaf(z3.z, w3.z, v); v = fmaf(z3.w, w3.w, v);
            out[X_OFF + (size_t)(rbase + rr) * FDIM + col] = v;
        }
    }
}

// ---------------------------------------------------------------------------
extern "C" void kernel_launch(void* const* d_in, const int* in_sizes, int n_in,
                              void* d_out, int out_size)
{
    const float* x       = (const float*)d_in[0];
    const float* W_enc   = (const float*)d_in[1];
    const float* b_enc   = (const float*)d_in[2];
    const float* W_dec   = (const float*)d_in[3];
    const float* b_dec   = (const float*)d_in[4];
    const float* W_sindy = (const float*)d_in[5];
    const float* b_sindy = (const float*)d_in[6];
    float* out = (float*)d_out;

    float* z_out = out + Z_OFF;

    encoder_kernel<<<385, 256>>>(x, W_enc, b_enc, W_sindy, z_out, out);
    hilbert_kernel<<<384, 1024>>>(W_enc, out);

    static int smem_set = 0;
    if (!smem_set) {
        cudaFuncSetAttribute(fused_kernel,
                             cudaFuncAttributeMaxDynamicSharedMemorySize,
                             FUSED_SMEM_BYTES);
        smem_set = 1;
    }
    fused_kernel<<<1025, 256, FUSED_SMEM_BYTES>>>(
        W_enc, W_dec, b_dec, W_sindy, b_sindy, z_out, out);
}

// round 12
// speedup vs baseline: 2.3457x; 1.0654x over previous
#include <cuda_runtime.h>
#include <math.h>

#define BDIM   16
#define TDIM   2048
#define FDIM   128
#define LDIM   16
#define LIB    1016
#define NROWS  (BDIM*TDIM)          // 32768

// output offsets (floats)
#define Y_OFF   ((size_t)0)
#define X_OFF   ((size_t)524288)
#define Z_OFF   ((size_t)4718592)
#define J_OFF   ((size_t)5242880)
#define WS_OFF  ((size_t)72351744)
#define WD_OFF  ((size_t)72368000)

// jac float4 regions: encoder 96MB | hilbert 108MB | fused 52MB
#define JAC_E_BEG ((size_t)0)
#define JAC_E_LEN ((size_t)6291456)    // 384 blocks * 16384
#define JAC_H_BEG ((size_t)6291456)
#define JAC_H_LEN ((size_t)7077888)    // 128 blocks * 55296
#define JAC_F_BEG ((size_t)13369344)
#define JAC_F_LEN ((size_t)3407872)    // 1024 blocks * 3328

// scratch
__device__ float g_amp[BDIM*LDIM*TDIM];          // [B,L,T]
__device__ float g_ang[BDIM*LDIM*TDIM];          // [B,L,T]
__device__ float g_zt [BDIM*LDIM*TDIM];          // [B,L,T]
__device__ __align__(16) float g_Wt[LIB*LDIM];   // W_sindy transposed [d][l]
__device__ unsigned int g_combo[LIB];            // packed (i | j<<8 | k<<16); 49 -> 1.0

// fused smem (floats): Wt 16256 | union{ f 1696 + combo 1016 , red 2048 }
// total 16256 + 2712 = 18968 fl = 75872 B  -> 3 blocks/SM
#define SM_F      16256
#define SM_COMBO  (16256 + 1696)
#define SM_RED    16256               // red reuses f/combo region after Y loop
#define FUSED_SMEM_BYTES ((16256 + 1696 + 1016) * 4)

// ---------------------------------------------------------------------------
__device__ __forceinline__ void jac_store(float* __restrict__ out,
                                          const float4* __restrict__ tile,
                                          size_t region_beg, size_t region_len,
                                          int jb, int nblk, int tid, int nthr)
{
    float4* jac4 = (float4*)(out + J_OFF);
    const size_t stride = (size_t)nblk * nthr;
    for (size_t v = (size_t)jb * nthr + tid; v < region_len; v += stride) {
        size_t gidx = region_beg + v;
        __stcs(&jac4[gidx], tile[gidx & 511]);
    }
}

// ---------------------------------------------------------------------------
// K1: encoder. blocks [0,128): z = x @ W_enc^T + b_enc, ONE thread per row.
//     block 128: transpose W_sindy -> g_Wt + combo table.
//     blocks [129,513): jac region E (96 MB, drains behind compute).
// ---------------------------------------------------------------------------
__global__ __launch_bounds__(256) void encoder_kernel(
    const float* __restrict__ x, const float* __restrict__ W_enc,
    const float* __restrict__ b_enc, const float* __restrict__ W_sindy,
    float* __restrict__ z_out, float* __restrict__ out)
{
    __shared__ float4 sW[512];
    __shared__ float  sb[16];
    const int tid = threadIdx.x;
    const int bb  = blockIdx.x;

    if (bb == 128) {
        for (int i = tid; i < LDIM * LIB; i += 256) {
            int l = i / LIB;
            int d = i - l * LIB;
            g_Wt[d * 16 + l] = W_sindy[i];
        }
        if (tid < 16) {
            int off = 152;
            for (int a = 0; a < tid; a++) { int n = 16 - a; off += n * (n + 1) / 2; }
            for (int j = tid; j < 16; j++)
                for (int k = j; k < 16; k++)
                    g_combo[off++] = (unsigned)tid | ((unsigned)j << 8) | ((unsigned)k << 16);
        } else if (tid == 16) {
            int d = 0;
            for (int i = 0; i < 16; i++)
                g_combo[d++] = (unsigned)i | (49u << 8) | (49u << 16);
            for (int i = 0; i < 16; i++)
                for (int j = i; j < 16; j++)
                    g_combo[d++] = (unsigned)i | ((unsigned)j << 8) | (49u << 16);
        } else if (tid == 17) {
            int d = 968;
            for (int i = 0; i < 48; i++)
                g_combo[d++] = (unsigned)i | (49u << 8) | (49u << 16);
        }
        return;
    }

    for (int i = tid; i < 512; i += 256) sW[i] = ((const float4*)W_enc)[i];

    if (bb >= 129) {
        __syncthreads();
        jac_store(out, sW, JAC_E_BEG, JAC_E_LEN, bb - 129, 384, tid, 256);
        return;
    }

    if (tid < 16) sb[tid] = b_enc[tid];
    __syncthreads();

    const int row = bb * 256 + tid;
    const float4* xr = (const float4*)(x + (size_t)row * FDIM);

    float acc[16];
#pragma unroll
    for (int l = 0; l < 16; l++) acc[l] = sb[l];

#pragma unroll 4
    for (int c = 0; c < 32; c++) {
        float4 xv = xr[c];
#pragma unroll
        for (int l = 0; l < 16; l++) {
            float4 wv = sW[l * 32 + c];
            acc[l] = fmaf(xv.x, wv.x, acc[l]);
            acc[l] = fmaf(xv.y, wv.y, acc[l]);
            acc[l] = fmaf(xv.z, wv.z, acc[l]);
            acc[l] = fmaf(xv.w, wv.w, acc[l]);
        }
    }
    float4* zo = (float4*)(z_out + (size_t)row * LDIM);
    zo[0] = make_float4(acc[0],  acc[1],  acc[2],  acc[3]);
    zo[1] = make_float4(acc[4],  acc[5],  acc[6],  acc[7]);
    zo[2] = make_float4(acc[8],  acc[9],  acc[10], acc[11]);
    zo[3] = make_float4(acc[12], acc[13], acc[14], acc[15]);

    const int b = row >> 11;
    const int t = row & 2047;
#pragma unroll
    for (int k = 0; k < 16; k++)
        g_zt[((size_t)(b * 16 + k)) * TDIM + t] = acc[k];
}

// ---------------------------------------------------------------------------
// K2: hilbert+X. blocks [0,256): 2048-pt FFT->filter->iFFT (1 bfly/thr/stage).
//     blocks [256,384): jac region H (108 MB).
//     blocks [384,512): X role — x_hat = z @ W_dec^T + b_dec (needs only z).
// ---------------------------------------------------------------------------
__global__ __launch_bounds__(1024) void hilbert_kernel(
    const float* __restrict__ W_enc,
    const float* __restrict__ W_dec, const float* __restrict__ b_dec,
    const float* __restrict__ z, float* __restrict__ out)
{
    __shared__ float2 bufA[2048];
    __shared__ float2 bufB[2048];
    const int tid = threadIdx.x;
    const int bb  = blockIdx.x;

    if (bb >= 384) {
        // ---- X role: rows [g*256, +256), 8 row-groups x 128 cols ----
        const int g   = bb - 384;
        const int col = tid & 127;
        const int rg  = tid >> 7;         // 0..7
        const float4* wd = (const float4*)W_dec;
        float4 w0 = wd[col * 4 + 0];
        float4 w1 = wd[col * 4 + 1];
        float4 w2 = wd[col * 4 + 2];
        float4 w3 = wd[col * 4 + 3];
        float  bd = b_dec[col];
        const int rbase = g * 256 + rg * 32;
#pragma unroll 4
        for (int rr = 0; rr < 32; rr++) {
            const float4* zr = (const float4*)(z + (size_t)(rbase + rr) * LDIM);
            float4 z0 = __ldg(zr + 0), z1 = __ldg(zr + 1);
            float4 z2 = __ldg(zr + 2), z3 = __ldg(zr + 3);
            float v = bd;
            v = fmaf(z0.x, w0.x, v); v = fmaf(z0.y, w0.y, v);
            v = fmaf(z0.z, w0.z, v); v = fmaf(z0.w, w0.w, v);
            v = fmaf(z1.x, w1.x, v); v = fmaf(z1.y, w1.y, v);
            v = fmaf(z1.z, w1.z, v); v = fmaf(z1.w, w1.w, v);
            v = fmaf(z2.x, w2.x, v); v = fmaf(z2.y, w2.y, v);
            v = fmaf(z2.z, w2.z, v); v = fmaf(z2.w, w2.w, v);
            v = fmaf(z3.x, w3.x, v); v = fmaf(z3.y, w3.y, v);
            v = fmaf(z3.z, w3.z, v); v = fmaf(z3.w, w3.w, v);
            out[X_OFF + (size_t)(rbase + rr) * FDIM + col] = v;
        }
        return;
    }

    if (bb >= 256) {
        float4* tile = (float4*)bufA;
        const float4* we4 = (const float4*)W_enc;
        if (tid < 512) tile[tid] = we4[tid];
        __syncthreads();
        jac_store(out, tile, JAC_H_BEG, JAC_H_LEN, bb - 256, 128, tid, 1024);
        return;
    }

    const int seq = bb;
    const float* zp = g_zt + (size_t)seq * TDIM;
    bufA[tid]        = make_float2(zp[tid], 0.0f);
    bufA[tid + 1024] = make_float2(zp[tid + 1024], 0.0f);
    __syncthreads();

    float2* src = bufA;
    float2* dst = bufB;

#pragma unroll 1
    for (int p = 0; p < 11; p++) {                 // forward FFT
        const int   len  = 1 << p;
        const float coef = -3.14159265358979323846f / (float)len;
        const int j = tid;
        const int k = j & (len - 1);
        float2 a  = src[j];
        float2 b2 = src[j + 1024];
        float s, c;
        __sincosf(coef * (float)k, &s, &c);
        float2 wb = make_float2(c * b2.x - s * b2.y, c * b2.y + s * b2.x);
        const int base = 2 * (j - k) + k;
        dst[base]       = make_float2(a.x + wb.x, a.y + wb.y);
        dst[base + len] = make_float2(a.x - wb.x, a.y - wb.y);
        __syncthreads();
        float2* tsw = src; src = dst; dst = tsw;
    }

    {   // H filter: H[0]=0, H[1..1023]=2, H[1024..2047]=0
        float h0 = (tid >= 1) ? 2.0f : 0.0f;
        src[tid].x *= h0;  src[tid].y *= h0;
        src[tid + 1024].x = 0.0f; src[tid + 1024].y = 0.0f;
    }
    __syncthreads();

#pragma unroll 1
    for (int p = 0; p < 11; p++) {                 // inverse FFT
        const int   len  = 1 << p;
        const float coef = 3.14159265358979323846f / (float)len;
        const int j = tid;
        const int k = j & (len - 1);
        float2 a  = src[j];
        float2 b2 = src[j + 1024];
        float s, c;
        __sincosf(coef * (float)k, &s, &c);
        float2 wb = make_float2(c * b2.x - s * b2.y, c * b2.y + s * b2.x);
        const int base = 2 * (j - k) + k;
        dst[base]       = make_float2(a.x + wb.x, a.y + wb.y);
        dst[base + len] = make_float2(a.x - wb.x, a.y - wb.y);
        __syncthreads();
        float2* tsw = src; src = dst; dst = tsw;
    }

    const float scale = 1.0f / 2048.0f;
    const size_t ob = (size_t)seq * TDIM;
#pragma unroll
    for (int it = 0; it < 2; it++) {
        int t = tid + it * 1024;
        float re = src[t].x * scale;
        float im = src[t].y * scale;
        g_amp[ob + t] = sqrtf(re * re + im * im);
        g_ang[ob + t] = atan2f(im, re);
    }
}

// ---------------------------------------------------------------------------
// K3: fused (Y + small jac). 1024 blocks x 256 thr, 3 blocks/SM (74.1 KB smem).
// Y: warp = feature octant (broadcast weights, f32x2 FMA), lane = row.
// Reduce: 3-round smem tree reusing the f/combo region (dead after Y loop).
// Block 1024: copy W_sindy, W_dec.
// ---------------------------------------------------------------------------
#define ADD2(dst, srcv) asm("add.rn.f32x2 %0,%0,%1;" : "+l"(dst) : "l"(srcv))

__global__ __launch_bounds__(256, 3) void fused_kernel(
    const float* __restrict__ W_enc,
    const float* __restrict__ W_dec,
    const float* __restrict__ W_sindy, const float* __restrict__ b_sindy,
    const float* __restrict__ z,       // z region of output blob [B,T,L]
    float* __restrict__ out)
{
    extern __shared__ float smem[];
    const int tid = threadIdx.x;
    const int bb  = blockIdx.x;

    if (bb == 1024) {
        const float4* ws4 = (const float4*)W_sindy;
        float4* o1 = (float4*)(out + WS_OFF);
        for (int i = tid; i < (LDIM * LIB) / 4; i += 256) o1[i] = ws4[i];
        const float4* wd4 = (const float4*)W_dec;
        float4* o2 = (float4*)(out + WD_OFF);
        for (int i = tid; i < (FDIM * LDIM) / 4; i += 256) o2[i] = wd4[i];
        return;
    }

    // ---- (1) jac slice: 3328 float4 per block (13/thread) ----
    {
        const float4* we4 = (const float4*)W_enc;
        float4* jac4 = (float4*)(out + J_OFF);
        const size_t vbase = JAC_F_BEG + (size_t)bb * 3328 + tid;
#pragma unroll 13
        for (int k = 0; k < 13; k++) {
            size_t v = vbase + (size_t)k * 256;
            __stcs(&jac4[v], __ldg(&we4[v & 511]));
        }
    }

    // ---- (2) smem fill ----
    float* s_Wt = smem;                       // [1016][16]
    float* s_f  = smem + SM_F;                // [32][53]
    unsigned int* s_combo = (unsigned int*)(smem + SM_COMBO);
    {
        const float4* wt4 = (const float4*)g_Wt;
        float4* d4 = (float4*)s_Wt;
        for (int i = tid; i < (LIB * LDIM) / 4; i += 256) d4[i] = wt4[i];
        for (int i = tid; i < LIB; i += 256) s_combo[i] = g_combo[i];
    }

    const int u    = tid >> 5;        // warp id = feature octant
    const int lane = tid & 31;        // row within tile
    const int row  = bb * 32 + lane;
    const int b    = row >> 11;
    const int tt   = row & 2047;
    float* f = s_f + lane * 53;
#pragma unroll
    for (int m = 0; m < 6; m++) {
        int idx = u * 6 + m;              // 0..47
        float val;
        if (idx < 16)      val = z[(size_t)row * LDIM + idx];
        else if (idx < 32) val = g_amp[((size_t)(b * 16 + idx - 16)) * TDIM + tt];
        else               val = g_ang[((size_t)(b * 16 + idx - 32)) * TDIM + tt];
        f[idx] = val;
    }
    if (u == 0) { f[48] = 1.0f; f[49] = 1.0f; f[50] = 1.0f; f[51] = 1.0f; f[52] = 1.0f; }
    __syncthreads();

    // ---- (3) Y: warp u walks d = u*127..u*127+126, packed f32x2 FMA ----
    unsigned long long A0 = 0, A1 = 0, A2 = 0, A3 = 0,
                       A4 = 0, A5 = 0, A6 = 0, A7 = 0;
    int d = u * 127;
#pragma unroll 2
    for (int s = 0; s < 127; s++, d++) {
        unsigned int c = s_combo[d];                       // broadcast
        float v = f[c & 63u] * f[(c >> 8) & 63u] * f[(c >> 16) & 63u];
        unsigned long long pk;
        asm("mov.b64 %0,{%1,%1};" : "=l"(pk) : "r"(__float_as_uint(v)));
        const ulonglong2* w2 = (const ulonglong2*)(s_Wt + (d << 4)); // broadcast
        ulonglong2 p0 = w2[0], p1 = w2[1];
        asm("fma.rn.f32x2 %0,%1,%2,%0;" : "+l"(A0) : "l"(pk), "l"(p0.x));
        asm("fma.rn.f32x2 %0,%1,%2,%0;" : "+l"(A1) : "l"(pk), "l"(p0.y));
        asm("fma.rn.f32x2 %0,%1,%2,%0;" : "+l"(A2) : "l"(pk), "l"(p1.x));
        asm("fma.rn.f32x2 %0,%1,%2,%0;" : "+l"(A3) : "l"(pk), "l"(p1.y));
        const ulonglong2* w3 = w2 + 2;
        ulonglong2 p2 = w3[0], p3 = w3[1];
        asm("fma.rn.f32x2 %0,%1,%2,%0;" : "+l"(A4) : "l"(pk), "l"(p2.x));
        asm("fma.rn.f32x2 %0,%1,%2,%0;" : "+l"(A5) : "l"(pk), "l"(p2.y));
        asm("fma.rn.f32x2 %0,%1,%2,%0;" : "+l"(A6) : "l"(pk), "l"(p3.x));
        asm("fma.rn.f32x2 %0,%1,%2,%0;" : "+l"(A7) : "l"(pk), "l"(p3.y));
    }
    __syncthreads();    // f/combo dead; region becomes reduce buffer

    float* s_red = smem + SM_RED;     // [4][32][16] max

    // round 1: warps 4-7 store, warps 0-3 add
    if (u >= 4) {
        ulonglong2* r2 = (ulonglong2*)(s_red + ((u - 4) * 32 + lane) * 16);
        ulonglong2 q;
        q.x = A0; q.y = A1; r2[0] = q;
        q.x = A2; q.y = A3; r2[1] = q;
        q.x = A4; q.y = A5; r2[2] = q;
        q.x = A6; q.y = A7; r2[3] = q;
    }
    __syncthreads();
    if (u < 4) {
        const ulonglong2* r2 = (const ulonglong2*)(s_red + (u * 32 + lane) * 16);
        ulonglong2 q0 = r2[0], q1 = r2[1], q2 = r2[2], q3 = r2[3];
        ADD2(A0, q0.x); ADD2(A1, q0.y); ADD2(A2, q1.x); ADD2(A3, q1.y);
        ADD2(A4, q2.x); ADD2(A5, q2.y); ADD2(A6, q3.x); ADD2(A7, q3.y);
    }
    __syncthreads();
    // round 2: warps 2-3 store, warps 0-1 add
    if (u == 2 || u == 3) {
        ulonglong2* r2 = (ulonglong2*)(s_red + ((u - 2) * 32 + lane) * 16);
        ulonglong2 q;
        q.x = A0; q.y = A1; r2[0] = q;
        q.x = A2; q.y = A3; r2[1] = q;
        q.x = A4; q.y = A5; r2[2] = q;
        q.x = A6; q.y = A7; r2[3] = q;
    }
    __syncthreads();
    if (u < 2) {
        const ulonglong2* r2 = (const ulonglong2*)(s_red + (u * 32 + lane) * 16);
        ulonglong2 q0 = r2[0], q1 = r2[1], q2 = r2[2], q3 = r2[3];
        ADD2(A0, q0.x); ADD2(A1, q0.y); ADD2(A2, q1.x); ADD2(A3, q1.y);
        ADD2(A4, q2.x); ADD2(A5, q2.y); ADD2(A6, q3.x); ADD2(A7, q3.y);
    }
    __syncthreads();
    // round 3: warp 1 stores, warp 0 adds + bias + output
    if (u == 1) {
        ulonglong2* r2 = (ulonglong2*)(s_red + lane * 16);
        ulonglong2 q;
        q.x = A0; q.y = A1; r2[0] = q;
        q.x = A2; q.y = A3; r2[1] = q;
        q.x = A4; q.y = A5; r2[2] = q;
        q.x = A6; q.y = A7; r2[3] = q;
    }
    __syncthreads();
    if (u == 0) {
        const ulonglong2* r2 = (const ulonglong2*)(s_red + lane * 16);
        ulonglong2 q0 = r2[0], q1 = r2[1], q2 = r2[2], q3 = r2[3];
        ADD2(A0, q0.x); ADD2(A1, q0.y); ADD2(A2, q1.x); ADD2(A3, q1.y);
        ADD2(A4, q2.x); ADD2(A5, q2.y); ADD2(A6, q3.x); ADD2(A7, q3.y);

        const float4* bs4 = (const float4*)b_sindy;
        float4 b0 = bs4[0], b1 = bs4[1], b2 = bs4[2], b3 = bs4[3];
        float2 v0 = *(float2*)&A0, v1 = *(float2*)&A1;
        float2 v2 = *(float2*)&A2, v3 = *(float2*)&A3;
        float2 v4 = *(float2*)&A4, v5 = *(float2*)&A5;
        float2 v6 = *(float2*)&A6, v7 = *(float2*)&A7;
        float4* yo = (float4*)(out + Y_OFF + (size_t)row * LDIM);
        yo[0] = make_float4(v0.x + b0.x, v0.y + b0.y, v1.x + b0.z, v1.y + b0.w);
        yo[1] = make_float4(v2.x + b1.x, v2.y + b1.y, v3.x + b1.z, v3.y + b1.w);
        yo[2] = make_float4(v4.x + b2.x, v4.y + b2.y, v5.x + b2.z, v5.y + b2.w);
        yo[3] = make_float4(v6.x + b3.x, v6.y + b3.y, v7.x + b3.z, v7.y + b3.w);
    }
}

// ---------------------------------------------------------------------------
extern "C" void kernel_launch(void* const* d_in, const int* in_sizes, int n_in,
                              void* d_out, int out_size)
{
    const float* x       = (const float*)d_in[0];
    const float* W_enc   = (const float*)d_in[1];
    const float* b_enc   = (const float*)d_in[2];
    const float* W_dec   = (const float*)d_in[3];
    const float* b_dec   = (const float*)d_in[4];
    const float* W_sindy = (const float*)d_in[5];
    const float* b_sindy = (const float*)d_in[6];
    float* out = (float*)d_out;

    float* z_out = out + Z_OFF;

    encoder_kernel<<<513, 256>>>(x, W_enc, b_enc, W_sindy, z_out, out);
    hilbert_kernel<<<512, 1024>>>(W_enc, W_dec, b_dec, z_out, out);

    static int smem_set = 0;
    if (!smem_set) {
        cudaFuncSetAttribute(fused_kernel,
                             cudaFuncAttributeMaxDynamicSharedMemorySize,
                             FUSED_SMEM_BYTES);
        smem_set = 1;
    }
    fused_kernel<<<1025, 256, FUSED_SMEM_BYTES>>>(
        W_enc, W_dec, W_sindy, b_sindy, z_out, out);
}